// round 1
// baseline (speedup 1.0000x reference)
#include <cuda_runtime.h>
#include <cuda_bf16.h>
#include <math.h>

// ---------------- problem constants ----------------
#define BB     2
#define SS     2048
#define NDIM   2048
#define NH     16
#define QRANK  1536
#define KVRANK 512
#define ROPE_D 64
#define NOPE_D 128
#define VDIM   128
#define QKH    192           // NOPE + ROPE
#define ROWS   (BB*SS)       // 4096
#define KVDIM  (NH*(NOPE_D+VDIM))  // 4096
#define QDIM   (NH*QKH)      // 3072
#define CDIM   (KVRANK+ROPE_D) // 576

// ---------------- scratch (device globals; no allocs allowed) ----------------
__device__ float g_cq  [ROWS*QRANK];   // 25 MB
__device__ float g_q   [ROWS*QDIM];    // 50 MB
__device__ float g_c   [ROWS*CDIM];    // 9.4 MB
__device__ float g_kvn [ROWS*KVRANK];  // 8.4 MB
__device__ float g_kv  [ROWS*KVDIM];   // 67 MB
__device__ float g_attn[ROWS*(NH*VDIM)]; // 33 MB

// ---------------- generic SGEMM: C[M,N] = A[M,K] * B[N,K]^T ----------------
// tile 128(M) x 64(N) x 16(K), 256 threads, 8x4 microtile.
#define GM 128
#define GN 64
#define GK 16

__global__ __launch_bounds__(256) void sgemm_nt(
    const float* __restrict__ A, const float* __restrict__ B,
    float* __restrict__ C, int M, int N, int K)
{
    __shared__ float As[GK][GM+4];   // pad -> ~2-way store conflicts only
    __shared__ float Bs[GK][GN+4];

    const int tid = threadIdx.x;
    const int tx  = tid & 15;        // N direction, 4 cols each
    const int ty  = tid >> 4;        // M direction, 8 rows each
    const int m0  = blockIdx.y * GM;
    const int n0  = blockIdx.x * GN;

    const int lc = tid & 15;         // k within tile
    const int lr = tid >> 4;         // row stripe

    const float* Ap = A + (size_t)(m0 + lr) * K + lc;
    const float* Bp = B + (size_t)(n0 + lr) * K + lc;

    float acc[8][4];
    #pragma unroll
    for (int i = 0; i < 8; i++)
        #pragma unroll
        for (int j = 0; j < 4; j++) acc[i][j] = 0.f;

    for (int k0 = 0; k0 < K; k0 += GK) {
        #pragma unroll
        for (int i = 0; i < 8; i++)
            As[lc][lr + 16*i] = Ap[(size_t)(16*i) * K + k0];
        #pragma unroll
        for (int i = 0; i < 4; i++)
            Bs[lc][lr + 16*i] = Bp[(size_t)(16*i) * K + k0];
        __syncthreads();

        #pragma unroll
        for (int kk = 0; kk < GK; kk++) {
            float4 a0 = *(const float4*)&As[kk][ty*8];
            float4 a1 = *(const float4*)&As[kk][ty*8 + 4];
            float4 b0 = *(const float4*)&Bs[kk][tx*4];
            float av[8] = {a0.x,a0.y,a0.z,a0.w,a1.x,a1.y,a1.z,a1.w};
            float bv[4] = {b0.x,b0.y,b0.z,b0.w};
            #pragma unroll
            for (int i = 0; i < 8; i++)
                #pragma unroll
                for (int j = 0; j < 4; j++)
                    acc[i][j] = fmaf(av[i], bv[j], acc[i][j]);
        }
        __syncthreads();
    }

    #pragma unroll
    for (int i = 0; i < 8; i++) {
        size_t row = (size_t)(m0 + ty*8 + i);
        float4 o = make_float4(acc[i][0], acc[i][1], acc[i][2], acc[i][3]);
        *(float4*)&C[row * N + n0 + tx*4] = o;
    }
}

// ---------------- RMSNorm: out[row, :L] = in[row, :L] * rsqrt(mean(x^2)+eps) * w ----------------
__global__ __launch_bounds__(256) void rmsnorm_k(
    const float* __restrict__ in, float* __restrict__ out,
    const float* __restrict__ w, int L, int sin, int sout)
{
    __shared__ float red[8];
    const int row = blockIdx.x;
    const float* ip = in + (size_t)row * sin;
    float ss = 0.f;
    for (int i = threadIdx.x; i < L; i += 256) {
        float v = ip[i];
        ss = fmaf(v, v, ss);
    }
    #pragma unroll
    for (int off = 16; off; off >>= 1)
        ss += __shfl_xor_sync(0xffffffffu, ss, off);
    if ((threadIdx.x & 31) == 0) red[threadIdx.x >> 5] = ss;
    __syncthreads();
    if (threadIdx.x == 0) {
        float tot = 0.f;
        #pragma unroll
        for (int i = 0; i < 8; i++) tot += red[i];
        red[0] = rsqrtf(tot / (float)L + 1e-6f);
    }
    __syncthreads();
    float inv = red[0];
    for (int i = threadIdx.x; i < L; i += 256)
        out[(size_t)row * sout + i] = ip[i] * inv * w[i];
}

// ---------------- RoPE ----------------
// q layout: g_q[row, h*192 + 128 + 2p {,+1}] ; freqs_cis: [S, 32, 2] (cos, sin)
__global__ void rope_q(float* __restrict__ q, const float* __restrict__ fc)
{
    int idx = blockIdx.x * blockDim.x + threadIdx.x;
    if (idx >= ROWS * NH * 32) return;
    int p = idx & 31;
    int h = (idx >> 5) & 15;
    int r = idx >> 9;
    int s = r & (SS - 1);
    float cs = fc[(s*32 + p)*2 + 0];
    float sn = fc[(s*32 + p)*2 + 1];
    float* base = q + (size_t)r * QDIM + h * QKH + NOPE_D + 2*p;
    float xr = base[0], xi = base[1];
    base[0] = xr*cs - xi*sn;
    base[1] = xr*sn + xi*cs;
}

__global__ void rope_k(float* __restrict__ c, const float* __restrict__ fc)
{
    int idx = blockIdx.x * blockDim.x + threadIdx.x;
    if (idx >= ROWS * 32) return;
    int p = idx & 31;
    int r = idx >> 5;
    int s = r & (SS - 1);
    float cs = fc[(s*32 + p)*2 + 0];
    float sn = fc[(s*32 + p)*2 + 1];
    float* base = c + (size_t)r * CDIM + KVRANK + 2*p;
    float xr = base[0], xi = base[1];
    base[0] = xr*cs - xi*sn;
    base[1] = xr*sn + xi*cs;
}

// ---------------- Flash attention (causal, online softmax) ----------------
// q tile 64 rows x d=192; k tile 32 x 192 (stored TRANSPOSED in smem, pad stride 34
// to avoid 16-way bank conflicts), v tile 32 x 128.
// 256 threads: ty=tid/16 owns 4 q-rows, tx=tid%16 owns 2 score-cols / 8 out-cols.
#define FAM 64
#define FAN 32
#define FAD 192
#define FAV 128
#define KTS 34   // transposed-K row stride (floats), even for float2 alignment

#define FA_SMEM_FLOATS (FAM*FAD + FAD*KTS + FAN*FAV + FAM*FAN + 2*FAM)

__global__ __launch_bounds__(256) void flash_attn(
    const float* __restrict__ gq, const float* __restrict__ gkv,
    const float* __restrict__ gc, float* __restrict__ gout)
{
    extern __shared__ float sm[];
    float* Qs = sm;                  // [64][192]
    float* KT = Qs + FAM*FAD;        // [192][34] transposed K
    float* Vs = KT + FAD*KTS;        // [32][128]
    float* Ps = Vs + FAN*FAV;        // [64][32]
    float* Ms = Ps + FAM*FAN;        // [64]
    float* Ls = Ms + FAM;            // [64]

    const int tid = threadIdx.x;
    const int tx = tid & 15, ty = tid >> 4;
    const int q0 = blockIdx.x * FAM;
    const int h  = blockIdx.y;
    const int b  = blockIdx.z;
    const int rb = b * SS;

    // load Q tile (qf = [nope | roped pe] is contiguous per head in g_q)
    const float* qp = gq + (size_t)(rb + q0) * QDIM + h * QKH;
    for (int i = tid; i < FAM*FAD; i += 256) {
        int r = i / FAD, c = i - r * FAD;
        Qs[i] = qp[(size_t)r * QDIM + c];
    }
    if (tid < FAM) { Ms[tid] = -INFINITY; Ls[tid] = 0.f; }

    float acc[4][8];
    #pragma unroll
    for (int i = 0; i < 4; i++)
        #pragma unroll
        for (int j = 0; j < 8; j++) acc[i][j] = 0.f;
    __syncthreads();

    const float scale = 0.07216878364870323f; // 1/sqrt(192)
    const int kend = q0 + FAM;

    for (int n0 = 0; n0 < kend; n0 += FAN) {
        // K tile, transposed: KT[c*34 + j] = kf[n0+j][c]
        for (int i = tid; i < FAN*FAD; i += 256) {
            int j = i / FAD, c = i - j * FAD;
            size_t row = (size_t)(rb + n0 + j);
            float v = (c < NOPE_D)
                ? gkv[row * KVDIM + h*256 + c]
                : gc [row * CDIM  + KVRANK + (c - NOPE_D)];
            KT[c * KTS + j] = v;
        }
        // V tile
        for (int i = tid; i < FAN*FAV; i += 256) {
            int j = i >> 7, c = i & 127;
            Vs[i] = gkv[(size_t)(rb + n0 + j) * KVDIM + h*256 + NOPE_D + c];
        }
        __syncthreads();

        // scores: S[4 rows][2 cols] per thread
        float sc0[4] = {0,0,0,0}, sc1[4] = {0,0,0,0};
        for (int kk = 0; kk < FAD; kk += 4) {
            float qv[4][4];
            #pragma unroll
            for (int i = 0; i < 4; i++) {
                float4 t4 = *(const float4*)&Qs[(ty*4 + i) * FAD + kk];
                qv[i][0]=t4.x; qv[i][1]=t4.y; qv[i][2]=t4.z; qv[i][3]=t4.w;
            }
            #pragma unroll
            for (int u = 0; u < 4; u++) {
                float2 k2 = *(const float2*)&KT[(kk + u) * KTS + tx*2];
                #pragma unroll
                for (int i = 0; i < 4; i++) {
                    sc0[i] = fmaf(qv[i][u], k2.x, sc0[i]);
                    sc1[i] = fmaf(qv[i][u], k2.y, sc1[i]);
                }
            }
        }

        // online softmax update (rows owned per-warp: warp w owns rows 8w..8w+7)
        #pragma unroll
        for (int i = 0; i < 4; i++) {
            int row = ty*4 + i;
            int qi = q0 + row;
            int kj = n0 + tx*2;
            float s0 = (kj     <= qi) ? sc0[i]*scale : -INFINITY;
            float s1 = (kj + 1 <= qi) ? sc1[i]*scale : -INFINITY;
            float rm = fmaxf(s0, s1);
            #pragma unroll
            for (int off = 8; off; off >>= 1)
                rm = fmaxf(rm, __shfl_xor_sync(0xffffffffu, rm, off));
            float mold = Ms[row];
            float mnew = fmaxf(mold, rm);
            float p0 = __expf(s0 - mnew);
            float p1 = __expf(s1 - mnew);
            float rs = p0 + p1;
            #pragma unroll
            for (int off = 8; off; off >>= 1)
                rs += __shfl_xor_sync(0xffffffffu, rs, off);
            float alpha = __expf(mold - mnew);
            float lnew = Ls[row] * alpha + rs;
            if (tx == 0) { Ms[row] = mnew; Ls[row] = lnew; }
            *(float2*)&Ps[row * FAN + tx*2] = make_float2(p0, p1);
            #pragma unroll
            for (int c = 0; c < 8; c++) acc[i][c] *= alpha;
        }
        __syncthreads();

        // O += P @ V  (thread: 4 rows x 8 v-cols)
        for (int j = 0; j < FAN; j++) {
            float4 v0 = *(const float4*)&Vs[j * FAV + tx*8];
            float4 v1 = *(const float4*)&Vs[j * FAV + tx*8 + 4];
            #pragma unroll
            for (int i = 0; i < 4; i++) {
                float p = Ps[(ty*4 + i) * FAN + j];
                acc[i][0] = fmaf(p, v0.x, acc[i][0]);
                acc[i][1] = fmaf(p, v0.y, acc[i][1]);
                acc[i][2] = fmaf(p, v0.z, acc[i][2]);
                acc[i][3] = fmaf(p, v0.w, acc[i][3]);
                acc[i][4] = fmaf(p, v1.x, acc[i][4]);
                acc[i][5] = fmaf(p, v1.y, acc[i][5]);
                acc[i][6] = fmaf(p, v1.z, acc[i][6]);
                acc[i][7] = fmaf(p, v1.w, acc[i][7]);
            }
        }
        __syncthreads();
    }

    // finalize: O /= l, write to g_attn[row, h*128 + c]
    #pragma unroll
    for (int i = 0; i < 4; i++) {
        int row = ty*4 + i;
        float inv = 1.f / Ls[row];
        float* op = gout + (size_t)(rb + q0 + row) * (NH*VDIM) + h*VDIM + tx*8;
        *(float4*)op       = make_float4(acc[i][0]*inv, acc[i][1]*inv, acc[i][2]*inv, acc[i][3]*inv);
        *(float4*)(op + 4) = make_float4(acc[i][4]*inv, acc[i][5]*inv, acc[i][6]*inv, acc[i][7]*inv);
    }
}

// ---------------- launcher ----------------
extern "C" void kernel_launch(void* const* d_in, const int* in_sizes, int n_in,
                              void* d_out, int out_size)
{
    const float* x     = (const float*)d_in[0];
    const float* fc    = (const float*)d_in[1];
    const float* wq_a  = (const float*)d_in[2];
    const float* qnw   = (const float*)d_in[3];
    const float* wq_b  = (const float*)d_in[4];
    const float* wkv_a = (const float*)d_in[5];
    const float* kvnw  = (const float*)d_in[6];
    const float* wkv_b = (const float*)d_in[7];
    const float* wo    = (const float*)d_in[8];
    float* out = (float*)d_out;

    float *cq, *q, *c, *kvn, *kv, *attn;
    cudaGetSymbolAddress((void**)&cq,   g_cq);
    cudaGetSymbolAddress((void**)&q,    g_q);
    cudaGetSymbolAddress((void**)&c,    g_c);
    cudaGetSymbolAddress((void**)&kvn,  g_kvn);
    cudaGetSymbolAddress((void**)&kv,   g_kv);
    cudaGetSymbolAddress((void**)&attn, g_attn);

    // 1) cq = x @ wq_a^T               [4096,1536]
    sgemm_nt<<<dim3(QRANK/GN, ROWS/GM), 256>>>(x, wq_a, cq, ROWS, QRANK, NDIM);
    // 2) rmsnorm(cq) in place
    rmsnorm_k<<<ROWS, 256>>>(cq, cq, qnw, QRANK, QRANK, QRANK);
    // 3) q = cqn @ wq_b^T              [4096,3072]
    sgemm_nt<<<dim3(QDIM/GN, ROWS/GM), 256>>>(cq, wq_b, q, ROWS, QDIM, QRANK);
    // 4) c = x @ wkv_a^T               [4096,576]
    sgemm_nt<<<dim3(CDIM/GN, ROWS/GM), 256>>>(x, wkv_a, c, ROWS, CDIM, NDIM);
    // 5) kvn = rmsnorm(c[:, :512])
    rmsnorm_k<<<ROWS, 256>>>(c, kvn, kvnw, KVRANK, CDIM, KVRANK);
    // 6) kv = kvn @ wkv_b^T            [4096,4096]
    sgemm_nt<<<dim3(KVDIM/GN, ROWS/GM), 256>>>(kvn, wkv_b, kv, ROWS, KVDIM, KVRANK);
    // 7) RoPE on q_pe (in g_q) and k_pe (in g_c)
    rope_q<<<(ROWS*NH*32 + 255)/256, 256>>>(q, fc);
    rope_k<<<(ROWS*32   + 255)/256, 256>>>(c, fc);
    // 8) flash attention -> g_attn     [4096, 2048]
    const int fa_bytes = FA_SMEM_FLOATS * (int)sizeof(float);
    cudaFuncSetAttribute(flash_attn, cudaFuncAttributeMaxDynamicSharedMemorySize, fa_bytes);
    flash_attn<<<dim3(SS/FAM, NH, BB), 256, fa_bytes>>>(q, kv, c, attn);
    // 9) out = attn @ wo^T             [4096, 2048]
    sgemm_nt<<<dim3(NDIM/GN, ROWS/GM), 256>>>(attn, wo, out, ROWS, NDIM, NH*VDIM);
}